// round 10
// baseline (speedup 1.0000x reference)
#include <cuda_runtime.h>

// VanillaSSM via exact diagonal recurrence (== reference FFT conv).
// Structure exploited: when A_bar[d,:] is uniform in n (true here: log_A==0),
// all 64 states of a d are identical => y = K_d*u + D_d*x with ONE scalar
// recurrence u(l) = a*u(l-1) + x(l) per (b,d). Verified on-device; general
// scan kernel is the fallback (exactly one path does work per launch).
//
// Fast path is a chunked scan for parallelism (exact, no truncation):
//   A: per (b,d,chunk) end-state S_c = sum_i a^(CH-1-i) x_i   (reads x;
//      last chunk skipped -- its carry is never consumed)
//   B: u0(c) = Horner(a^CH, S_0..S_{c-1}); replay chunk, write y.
// C=8 chunks of 256 -> 65536 independent streams (~14 warps/SM in flight).

namespace {

constexpr int BATCH   = 8;
constexpr int L       = 2048;
constexpr int D_MODEL = 1024;
constexpr int NSTATE  = 64;
constexpr float DT    = 0.1f;

constexpr int C  = 8;            // chunks per sequence
constexpr int CH = L / C;        // 256 steps per chunk

// ---------------- scratch (persistent; rewritten every launch) -----------
__device__ float g_K[D_MODEL];
__device__ float g_a[D_MODEL];
__device__ int   g_uni[8];
__device__ float g_S[BATCH * C * D_MODEL];   // chunk end-states

// ---------------- packed f32x2 helpers (general fallback) ----------------
__device__ __forceinline__ unsigned long long pack2(float lo, float hi) {
    unsigned long long r;
    asm("mov.b64 %0, {%1, %2};" : "=l"(r) : "f"(lo), "f"(hi));
    return r;
}
__device__ __forceinline__ void unpack2(unsigned long long v, float& lo, float& hi) {
    asm("mov.b64 {%0, %1}, %2;" : "=f"(lo), "=f"(hi) : "l"(v));
}
__device__ __forceinline__ unsigned long long mul2(unsigned long long a, unsigned long long b) {
    unsigned long long r;
    asm("mul.rn.f32x2 %0, %1, %2;" : "=l"(r) : "l"(a), "l"(b));
    return r;
}
__device__ __forceinline__ unsigned long long fma2(unsigned long long a, unsigned long long b,
                                                   unsigned long long c) {
    unsigned long long r;
    asm("fma.rn.f32x2 %0, %1, %2, %3;" : "=l"(r) : "l"(a), "l"(b), "l"(c));
    return r;
}

__device__ __forceinline__ bool all_uniform() {
    int u = 1;
#pragma unroll
    for (int i = 0; i < 8; ++i) u &= g_uni[i];
    return u != 0;
}

// ================= setup: coefficients + uniformity check ================
// 8 blocks x 1024 threads: 8 threads per d, 8 states per thread.
__global__ __launch_bounds__(1024)
void ssm_setup_kernel(const float* __restrict__ log_A,
                      const float* __restrict__ Bp,
                      const float* __restrict__ Cp)
{
    __shared__ int s_uni;
    if (threadIdx.x == 0) s_uni = 1;
    __syncthreads();

    const int tid  = threadIdx.x;
    const int d    = blockIdx.x * 128 + (tid >> 3);
    const int n0   = (tid & 7) * 8;
    const int base = d * NSTATE + n0;

    const float4 la0 = *(const float4*)&log_A[base];
    const float4 la1 = *(const float4*)&log_A[base + 4];
    const float4 bp0 = *(const float4*)&Bp[base];
    const float4 bp1 = *(const float4*)&Bp[base + 4];
    const float4 cp0 = *(const float4*)&Cp[base];
    const float4 cp1 = *(const float4*)&Cp[base + 4];

    float la[8] = {la0.x, la0.y, la0.z, la0.w, la1.x, la1.y, la1.z, la1.w};
    float bp[8] = {bp0.x, bp0.y, bp0.z, bp0.w, bp1.x, bp1.y, bp1.z, bp1.w};
    float cp[8] = {cp0.x, cp0.y, cp0.z, cp0.w, cp1.x, cp1.y, cp1.z, cp1.w};

    float K = 0.0f, a[8];
    bool uni = true;
#pragma unroll
    for (int j = 0; j < 8; ++j) {
        const float A = -expf(la[j]);
        a[j] = expf(DT * A);
        K += (a[j] - 1.0f) / A * bp[j] * cp[j];
        uni = uni && (__float_as_int(a[j]) == __float_as_int(a[0]));
    }
    // compare against the d-group leader's a (lanes tid&~7 .. +7 share a d)
    const float aref = __shfl_sync(0xFFFFFFFFu, a[0], (tid & 31) & ~7);
    uni = uni && (__float_as_int(a[0]) == __float_as_int(aref));

    // sum K over the 8-lane group
#pragma unroll
    for (int off = 1; off < 8; off <<= 1)
        K += __shfl_xor_sync(0xFFFFFFFFu, K, off);

    if ((tid & 7) == 0) { g_K[d] = K; g_a[d] = aref; }
    if (__ballot_sync(0xFFFFFFFFu, !uni) != 0) s_uni = 0;   // benign race
    __syncthreads();
    if (threadIdx.x == 0) g_uni[blockIdx.x] = s_uni;
}

// ================= fast path A: chunk end-states =========================
// grid (D_MODEL/256, C-1, BATCH), block 256: thread -> (b, chunk, d).
__global__ __launch_bounds__(256)
void ssm_carry_kernel(const float* __restrict__ x)
{
    if (!all_uniform()) return;

    const int d = blockIdx.x * 256 + threadIdx.x;
    const int c = blockIdx.y;
    const int b = blockIdx.z;
    const float a = g_a[d];

    const float* xg = x + ((long)b * L + c * CH) * D_MODEL + d;

    float u = 0.0f;
#pragma unroll 8
    for (int i = 0; i < CH; ++i)
        u = fmaf(a, u, xg[i * D_MODEL]);

    g_S[(b * C + c) * D_MODEL + d] = u;
}

// ================= fast path B: seeded replay, writes y ==================
__global__ __launch_bounds__(256)
void ssm_fast_kernel(const float* __restrict__ x,
                     const float* __restrict__ Dp,
                     float* __restrict__ y)
{
    if (!all_uniform()) return;

    const int d = blockIdx.x * 256 + threadIdx.x;
    const int c = blockIdx.y;
    const int b = blockIdx.z;

    const float a  = g_a[d];
    const float K  = g_K[d];
    const float Dd = Dp[d];

    // a^CH via squarings (CH = 256 = 2^8)
    float ap = a;
#pragma unroll
    for (int k = 0; k < 8; ++k) ap *= ap;

    // exact seed: u0 = sum_{j<c} ap^(c-1-j) * S_j   (Horner)
    float u = 0.0f;
    for (int j = 0; j < c; ++j)
        u = fmaf(ap, u, g_S[(b * C + j) * D_MODEL + d]);

    const float* xg = x + ((long)b * L + c * CH) * D_MODEL + d;
    float*       yg = y + ((long)b * L + c * CH) * D_MODEL + d;

#pragma unroll 8
    for (int i = 0; i < CH; ++i) {
        const float xv = xg[i * D_MODEL];
        u = fmaf(a, u, xv);
        yg[i * D_MODEL] = fmaf(Dd, xv, K * u);
    }
}

// ================= general fallback (proven R5 kernel) ===================
constexpr int T       = 32;
constexpr int NROUNDS = L / T;
constexpr int THREADS = 64;
constexpr int XSTR    = 40;

__global__ __launch_bounds__(THREADS)
void ssm_scan_kernel(const float* __restrict__ x,
                     const float* __restrict__ log_A,
                     const float* __restrict__ Bp,
                     const float* __restrict__ Cp,
                     const float* __restrict__ Dp,
                     float* __restrict__ y)
{
    if (all_uniform()) return;    // fast path handled everything

    __shared__ float xs[2][2][4 * XSTR];

    const int b    = blockIdx.y;
    const int tid  = threadIdx.x;
    const int w    = tid >> 5;
    const int lane = tid & 31;
    const int g    = lane >> 3;
    const int gl   = lane & 7;
    const int d0w  = blockIdx.x * 8 + w * 4;
    const int d    = d0w + g;

    unsigned long long a01[4], k01[4];
    {
        const int cb = d * NSTATE + gl * 4;
        const float4 laL = *(const float4*)&log_A[cb];
        const float4 laH = *(const float4*)&log_A[cb + 32];
        const float4 bL  = *(const float4*)&Bp[cb];
        const float4 bH  = *(const float4*)&Bp[cb + 32];
        const float4 cL  = *(const float4*)&Cp[cb];
        const float4 cH  = *(const float4*)&Cp[cb + 32];
        const float* laLp = &laL.x; const float* laHp = &laH.x;
        const float* bLp  = &bL.x;  const float* bHp  = &bH.x;
        const float* cLp  = &cL.x;  const float* cHp  = &cH.x;
#pragma unroll
        for (int j = 0; j < 4; ++j) {
            const float AL = -expf(laLp[j]);
            const float AH = -expf(laHp[j]);
            const float aL = expf(DT * AL);
            const float aH = expf(DT * AH);
            a01[j] = pack2(aL, aH);
            k01[j] = pack2((aL - 1.0f) / AL * bLp[j] * cLp[j],
                           (aH - 1.0f) / AH * bHp[j] * cHp[j]);
        }
    }

    const int si = lane >> 2;
    const int sj = lane & 3;
    const float Dd = Dp[d0w + sj];
    const float* xg = x + (long)b * L * D_MODEL + d0w + sj;
    float*       yg = y + (long)b * L * D_MODEL + d0w + sj;

    float xpre[4], xcur[4];
#pragma unroll
    for (int k = 0; k < 4; ++k)
        xpre[k] = xg[(si + 8 * k) * D_MODEL];

    unsigned long long u0 = 0ull, u1 = 0ull, u2 = 0ull, u3 = 0ull;

    for (int r = 0; r < NROUNDS; ++r) {
        const int l0 = r * T;
        float* xb = xs[w][r & 1];
#pragma unroll
        for (int k = 0; k < 4; ++k) {
            xcur[k] = xpre[k];
            xb[sj * XSTR + si + 8 * k] = xpre[k];
        }
        __syncwarp();
        if (r + 1 < NROUNDS) {
#pragma unroll
            for (int k = 0; k < 4; ++k)
                xpre[k] = xg[(l0 + T + si + 8 * k) * D_MODEL];
        }

        float y_out[4];
#pragma unroll
        for (int tb = 0; tb < T; tb += 16) {
            float v[16];
#pragma unroll
            for (int q = 0; q < 16; q += 4) {
                const float4 xq = *(const float4*)&xb[g * XSTR + tb + q];
                const float* xe = &xq.x;
#pragma unroll
                for (int i2 = 0; i2 < 4; ++i2) {
                    const unsigned long long xx = pack2(xe[i2], xe[i2]);
                    u0 = fma2(a01[0], u0, xx);
                    u1 = fma2(a01[1], u1, xx);
                    u2 = fma2(a01[2], u2, xx);
                    u3 = fma2(a01[3], u3, xx);
                    unsigned long long acc = mul2(k01[0], u0);
                    acc = fma2(k01[1], u1, acc);
                    acc = fma2(k01[2], u2, acc);
                    float lo, hi;
                    unpack2(fma2(k01[3], u3, acc), lo, hi);
                    v[q + i2] = lo + hi;
                }
            }
            {
                const bool h4 = (gl & 4) != 0;
#pragma unroll
                for (int ii = 0; ii < 8; ++ii) {
                    const int i = (ii < 4) ? ii : ii + 4;
                    const float send = h4 ? v[i] : v[i + 4];
                    const float keep = h4 ? v[i + 4] : v[i];
                    v[i] = keep + __shfl_xor_sync(0xFFFFFFFFu, send, 4);
                }
                const bool h2 = (gl & 2) != 0;
#pragma unroll
                for (int ii = 0; ii < 4; ++ii) {
                    const int i = (ii < 2) ? ii : ii + 6;
                    const float send = h2 ? v[i] : v[i + 2];
                    const float keep = h2 ? v[i + 2] : v[i];
                    v[i] = keep + __shfl_xor_sync(0xFFFFFFFFu, send, 2);
                }
                const bool h1 = (gl & 1) != 0;
#pragma unroll
                for (int ii = 0; ii < 2; ++ii) {
                    const int i = ii * 8;
                    const float send = h1 ? v[i] : v[i + 1];
                    const float keep = h1 ? v[i + 1] : v[i];
                    v[i] = keep + __shfl_xor_sync(0xFFFFFFFFu, send, 1);
                }
            }
            const int srcLane = sj * 8 + si;
            y_out[tb / 8]     = __shfl_sync(0xFFFFFFFFu, v[0], srcLane);
            y_out[tb / 8 + 1] = __shfl_sync(0xFFFFFFFFu, v[8], srcLane);
        }
#pragma unroll
        for (int k = 0; k < 4; ++k)
            yg[(l0 + si + 8 * k) * D_MODEL] = fmaf(Dd, xcur[k], y_out[k]);
    }
}

} // namespace

extern "C" void kernel_launch(void* const* d_in, const int* in_sizes, int n_in,
                              void* d_out, int out_size)
{
    const float* x     = (const float*)d_in[0];
    const float* log_A = (const float*)d_in[1];
    const float* Bp    = (const float*)d_in[2];
    const float* Cp    = (const float*)d_in[3];
    const float* Dp    = (const float*)d_in[4];
    float* y           = (float*)d_out;

    ssm_setup_kernel<<<8, 1024>>>(log_A, Bp, Cp);

    dim3 agrid(D_MODEL / 256, C - 1, BATCH);    // last chunk's carry unused
    ssm_carry_kernel<<<agrid, 256>>>(x);
    dim3 bgrid(D_MODEL / 256, C, BATCH);
    ssm_fast_kernel<<<bgrid, 256>>>(x, Dp, y);

    dim3 sgrid(D_MODEL / 8, BATCH);
    ssm_scan_kernel<<<sgrid, THREADS>>>(x, log_A, Bp, Cp, Dp, y);
}

// round 12
// speedup vs baseline: 1.0220x; 1.0220x over previous
#include <cuda_runtime.h>

// VanillaSSM via exact diagonal recurrence (== reference FFT conv).
// When A_bar[d,:] is uniform in n (true here: log_A==0), all 64 states of a
// d are equal => y = K_d*u + D_d*x with ONE scalar recurrence per (b,d).
// Verified on-device; general scan is the else-branch of the SAME kernel.
//
// Fused fast path (single kernel, exact):
//   pass1: block (b,c,dg) computes chunk end-state S_c from x, publishes
//          (flag per (b,c,dgroup); chunk C-1 skips -- carry never consumed)
//   seed:  spin on predecessor flags; u0 = Horner(a^CH, S_0..S_{c-1})
//   pass2: replay own chunk (L2-hot: block just read it) and write y.
// 256 blocks x 256 threads -> all co-resident (no spin deadlock).

namespace {

constexpr int BATCH   = 8;
constexpr int L       = 2048;
constexpr int D_MODEL = 1024;
constexpr int NSTATE  = 64;
constexpr float DT    = 0.1f;

constexpr int C   = 8;           // chunks per sequence
constexpr int CH  = L / C;       // 256 steps per chunk
constexpr int DG  = 4;           // d-groups
constexpr int DPG = D_MODEL / DG;

// ---------------- scratch (persistent; rewritten every launch) -----------
__device__ float g_K[D_MODEL];
__device__ float g_a[D_MODEL];
__device__ int   g_uni[8];
__device__ float g_S[BATCH * C * D_MODEL];      // chunk end-states
__device__ int   g_flag[BATCH * C * DG];        // carry-ready flags (256)

// ---------------- packed f32x2 helpers (general fallback) ----------------
__device__ __forceinline__ unsigned long long pack2(float lo, float hi) {
    unsigned long long r;
    asm("mov.b64 %0, {%1, %2};" : "=l"(r) : "f"(lo), "f"(hi));
    return r;
}
__device__ __forceinline__ void unpack2(unsigned long long v, float& lo, float& hi) {
    asm("mov.b64 {%0, %1}, %2;" : "=f"(lo), "=f"(hi) : "l"(v));
}
__device__ __forceinline__ unsigned long long mul2(unsigned long long a, unsigned long long b) {
    unsigned long long r;
    asm("mul.rn.f32x2 %0, %1, %2;" : "=l"(r) : "l"(a), "l"(b));
    return r;
}
__device__ __forceinline__ unsigned long long fma2(unsigned long long a, unsigned long long b,
                                                   unsigned long long c) {
    unsigned long long r;
    asm("fma.rn.f32x2 %0, %1, %2, %3;" : "=l"(r) : "l"(a), "l"(b), "l"(c));
    return r;
}

__device__ __forceinline__ bool all_uniform() {
    int u = 1;
#pragma unroll
    for (int i = 0; i < 8; ++i) u &= g_uni[i];
    return u != 0;
}

// ================= setup: coefficients + uniformity + flag reset =========
// 8 blocks x 1024 threads: 8 threads per d, 8 states per thread.
__global__ __launch_bounds__(1024)
void ssm_setup_kernel(const float* __restrict__ log_A,
                      const float* __restrict__ Bp,
                      const float* __restrict__ Cp)
{
    __shared__ int s_uni;
    if (threadIdx.x == 0) s_uni = 1;
    __syncthreads();

    const int tid  = threadIdx.x;
    if (blockIdx.x == 0 && tid < BATCH * C * DG) g_flag[tid] = 0;

    const int d    = blockIdx.x * 128 + (tid >> 3);
    const int n0   = (tid & 7) * 8;
    const int base = d * NSTATE + n0;

    const float4 la0 = *(const float4*)&log_A[base];
    const float4 la1 = *(const float4*)&log_A[base + 4];
    const float4 bp0 = *(const float4*)&Bp[base];
    const float4 bp1 = *(const float4*)&Bp[base + 4];
    const float4 cp0 = *(const float4*)&Cp[base];
    const float4 cp1 = *(const float4*)&Cp[base + 4];

    float la[8] = {la0.x, la0.y, la0.z, la0.w, la1.x, la1.y, la1.z, la1.w};
    float bp[8] = {bp0.x, bp0.y, bp0.z, bp0.w, bp1.x, bp1.y, bp1.z, bp1.w};
    float cp[8] = {cp0.x, cp0.y, cp0.z, cp0.w, cp1.x, cp1.y, cp1.z, cp1.w};

    float K = 0.0f, a[8];
    bool uni = true;
#pragma unroll
    for (int j = 0; j < 8; ++j) {
        const float A = -expf(la[j]);
        a[j] = expf(DT * A);
        K += (a[j] - 1.0f) / A * bp[j] * cp[j];
        uni = uni && (__float_as_int(a[j]) == __float_as_int(a[0]));
    }
    const float aref = __shfl_sync(0xFFFFFFFFu, a[0], (tid & 31) & ~7);
    uni = uni && (__float_as_int(a[0]) == __float_as_int(aref));

#pragma unroll
    for (int off = 1; off < 8; off <<= 1)
        K += __shfl_xor_sync(0xFFFFFFFFu, K, off);

    if ((tid & 7) == 0) { g_K[d] = K; g_a[d] = aref; }
    if (__ballot_sync(0xFFFFFFFFu, !uni) != 0) s_uni = 0;   // benign race
    __syncthreads();
    if (threadIdx.x == 0) g_uni[blockIdx.x] = s_uni;
}

// ================= fused scan: fast chunked path + general fallback ======
constexpr int T    = 32;
constexpr int NR   = L / T;
constexpr int XSTR = 40;

__global__ __launch_bounds__(256)
void ssm_fused_kernel(const float* __restrict__ x,
                      const float* __restrict__ log_A,
                      const float* __restrict__ Bp,
                      const float* __restrict__ Cp,
                      const float* __restrict__ Dp,
                      float* __restrict__ y)
{
    __shared__ float xs[8][2][4 * XSTR];    // general path only (20 KB)

    const int tid = threadIdx.x;
    const int bid = blockIdx.x;

    if (all_uniform()) {
        // ---------------- fast path: chunked scan with in-kernel carries --
        const int dg = bid & (DG - 1);
        const int c  = (bid >> 2) & (C - 1);
        const int b  = bid >> 5;
        const int d  = dg * DPG + tid;

        const float a  = g_a[d];
        const float K  = g_K[d];
        const float Dd = Dp[d];

        const float* xc = x + ((long)b * L + c * CH) * D_MODEL + d;
        float*       yc = y + ((long)b * L + c * CH) * D_MODEL + d;

        // pass 1: own chunk end-state (skipped for last chunk: never used)
        if (c < C - 1) {
            float u = 0.0f;
#pragma unroll 8
            for (int i = 0; i < CH; ++i)
                u = fmaf(a, u, xc[i * D_MODEL]);
            g_S[(b * C + c) * D_MODEL + d] = u;
            __threadfence();
            __syncthreads();
            if (tid == 0)
                atomicExch(&g_flag[(b * C + c) * DG + dg], 1);
        }

        // a^CH via squarings (CH = 256 = 2^8)
        float ap = a;
#pragma unroll
        for (int k = 0; k < 8; ++k) ap *= ap;

        // wait for predecessors, then exact Horner seed
        float u = 0.0f;
        if (c > 0) {
            if (tid < c) {
                while (atomicAdd(&g_flag[(b * C + tid) * DG + dg], 0) == 0)
                    __nanosleep(128);
                __threadfence();
            }
            __syncthreads();
            for (int j = 0; j < c; ++j)
                u = fmaf(ap, u, g_S[(b * C + j) * D_MODEL + d]);
        }

        // pass 2: replay own chunk (L2-hot), write y
#pragma unroll 8
        for (int i = 0; i < CH; ++i) {
            const float xv = xc[i * D_MODEL];
            u = fmaf(a, u, xv);
            yc[i * D_MODEL] = fmaf(Dd, xv, K * u);
        }
        return;
    }

    // ---------------- general fallback (R5 logic, 8 warps / 32 d per blk) -
    const int b     = bid >> 5;
    const int d0blk = (bid & 31) * 32;
    const int w     = tid >> 5;
    const int lane  = tid & 31;
    const int g     = lane >> 3;
    const int gl    = lane & 7;
    const int d0w   = d0blk + w * 4;
    const int d     = d0w + g;

    unsigned long long a01[4], k01[4];
    {
        const int cb = d * NSTATE + gl * 4;
        const float4 laL = *(const float4*)&log_A[cb];
        const float4 laH = *(const float4*)&log_A[cb + 32];
        const float4 bL  = *(const float4*)&Bp[cb];
        const float4 bH  = *(const float4*)&Bp[cb + 32];
        const float4 cL  = *(const float4*)&Cp[cb];
        const float4 cH  = *(const float4*)&Cp[cb + 32];
        const float* laLp = &laL.x; const float* laHp = &laH.x;
        const float* bLp  = &bL.x;  const float* bHp  = &bH.x;
        const float* cLp  = &cL.x;  const float* cHp  = &cH.x;
#pragma unroll
        for (int j = 0; j < 4; ++j) {
            const float AL = -expf(laLp[j]);
            const float AH = -expf(laHp[j]);
            const float aL = expf(DT * AL);
            const float aH = expf(DT * AH);
            a01[j] = pack2(aL, aH);
            k01[j] = pack2((aL - 1.0f) / AL * bLp[j] * cLp[j],
                           (aH - 1.0f) / AH * bHp[j] * cHp[j]);
        }
    }

    const int si = lane >> 2;
    const int sj = lane & 3;
    const float Dd = Dp[d0w + sj];
    const float* xg = x + (long)b * L * D_MODEL + d0w + sj;
    float*       yg = y + (long)b * L * D_MODEL + d0w + sj;

    float xpre[4], xcur[4];
#pragma unroll
    for (int k = 0; k < 4; ++k)
        xpre[k] = xg[(si + 8 * k) * D_MODEL];

    unsigned long long u0 = 0ull, u1 = 0ull, u2 = 0ull, u3 = 0ull;

    for (int r = 0; r < NR; ++r) {
        const int l0 = r * T;
        float* xb = xs[w][r & 1];
#pragma unroll
        for (int k = 0; k < 4; ++k) {
            xcur[k] = xpre[k];
            xb[sj * XSTR + si + 8 * k] = xpre[k];
        }
        __syncwarp();
        if (r + 1 < NR) {
#pragma unroll
            for (int k = 0; k < 4; ++k)
                xpre[k] = xg[(l0 + T + si + 8 * k) * D_MODEL];
        }

        float y_out[4];
#pragma unroll
        for (int tb = 0; tb < T; tb += 16) {
            float v[16];
#pragma unroll
            for (int q = 0; q < 16; q += 4) {
                const float4 xq = *(const float4*)&xb[g * XSTR + tb + q];
                const float* xe = &xq.x;
#pragma unroll
                for (int i2 = 0; i2 < 4; ++i2) {
                    const unsigned long long xx = pack2(xe[i2], xe[i2]);
                    u0 = fma2(a01[0], u0, xx);
                    u1 = fma2(a01[1], u1, xx);
                    u2 = fma2(a01[2], u2, xx);
                    u3 = fma2(a01[3], u3, xx);
                    unsigned long long acc = mul2(k01[0], u0);
                    acc = fma2(k01[1], u1, acc);
                    acc = fma2(k01[2], u2, acc);
                    float lo, hi;
                    unpack2(fma2(k01[3], u3, acc), lo, hi);
                    v[q + i2] = lo + hi;
                }
            }
            {
                const bool h4 = (gl & 4) != 0;
#pragma unroll
                for (int ii = 0; ii < 8; ++ii) {
                    const int i = (ii < 4) ? ii : ii + 4;
                    const float send = h4 ? v[i] : v[i + 4];
                    const float keep = h4 ? v[i + 4] : v[i];
                    v[i] = keep + __shfl_xor_sync(0xFFFFFFFFu, send, 4);
                }
                const bool h2 = (gl & 2) != 0;
#pragma unroll
                for (int ii = 0; ii < 4; ++ii) {
                    const int i = (ii < 2) ? ii : ii + 6;
                    const float send = h2 ? v[i] : v[i + 2];
                    const float keep = h2 ? v[i + 2] : v[i];
                    v[i] = keep + __shfl_xor_sync(0xFFFFFFFFu, send, 2);
                }
                const bool h1 = (gl & 1) != 0;
#pragma unroll
                for (int ii = 0; ii < 2; ++ii) {
                    const int i = ii * 8;
                    const float send = h1 ? v[i] : v[i + 1];
                    const float keep = h1 ? v[i + 1] : v[i];
                    v[i] = keep + __shfl_xor_sync(0xFFFFFFFFu, send, 1);
                }
            }
            const int srcLane = sj * 8 + si;
            y_out[tb / 8]     = __shfl_sync(0xFFFFFFFFu, v[0], srcLane);
            y_out[tb / 8 + 1] = __shfl_sync(0xFFFFFFFFu, v[8], srcLane);
        }
#pragma unroll
        for (int k = 0; k < 4; ++k)
            yg[(l0 + si + 8 * k) * D_MODEL] = fmaf(Dd, xcur[k], y_out[k]);
    }
}

} // namespace

extern "C" void kernel_launch(void* const* d_in, const int* in_sizes, int n_in,
                              void* d_out, int out_size)
{
    const float* x     = (const float*)d_in[0];
    const float* log_A = (const float*)d_in[1];
    const float* Bp    = (const float*)d_in[2];
    const float* Cp    = (const float*)d_in[3];
    const float* Dp    = (const float*)d_in[4];
    float* y           = (float*)d_out;

    ssm_setup_kernel<<<8, 1024>>>(log_A, Bp, Cp);
    ssm_fused_kernel<<<DG * C * BATCH, 256>>>(x, log_A, Bp, Cp, Dp, y);
}

// round 13
// speedup vs baseline: 1.8153x; 1.7762x over previous
#include <cuda_runtime.h>

// VanillaSSM via exact diagonal recurrence (== reference FFT conv).
// When A_bar[d,:] is uniform in n (true here: log_A==0), all 64 states of a
// d are equal => y = K_d*u + D_d*x with ONE scalar recurrence per (b,d).
// Verified on-device; general scan is the else-branch of the SAME kernel.
//
// Fused fast path (single kernel, exact):
//   pass1: block (b,c,dg) computes chunk end-state S_c from x, publishes
//          (flag per (b,c,dg); chunk C-1 skips -- carry never consumed)
//   seed:  spin on predecessor flags; u0 = Horner(a^CH, S_0..S_{c-1})
//   pass2: replay own chunk (L2-hot: block just read it) and write y.
// C=16 chunks -> 512 blocks (~28 warps/SM) and 16-wide double-buffered
// register batches (per-thread MLP~16) to put >>BW*latency bytes in flight.
// Deadlock-free: every flag dependency points to a strictly lower blockIdx.

namespace {

constexpr int BATCH   = 8;
constexpr int L       = 2048;
constexpr int D_MODEL = 1024;
constexpr int NSTATE  = 64;
constexpr float DT    = 0.1f;

constexpr int C   = 16;          // chunks per sequence
constexpr int CH  = L / C;       // 128 steps per chunk
constexpr int NB  = CH / 16;     // 8 batches of 16
constexpr int DG  = 4;           // d-groups
constexpr int DPG = D_MODEL / DG;

// ---------------- scratch (persistent; rewritten every launch) -----------
__device__ float g_K[D_MODEL];
__device__ float g_a[D_MODEL];
__device__ int   g_uni[64];
__device__ float g_S[BATCH * C * D_MODEL];      // chunk end-states
__device__ int   g_flag[BATCH * C * DG];        // carry-ready flags (512)

// ---------------- packed f32x2 helpers (general fallback) ----------------
__device__ __forceinline__ unsigned long long pack2(float lo, float hi) {
    unsigned long long r;
    asm("mov.b64 %0, {%1, %2};" : "=l"(r) : "f"(lo), "f"(hi));
    return r;
}
__device__ __forceinline__ void unpack2(unsigned long long v, float& lo, float& hi) {
    asm("mov.b64 {%0, %1}, %2;" : "=f"(lo), "=f"(hi) : "l"(v));
}
__device__ __forceinline__ unsigned long long mul2(unsigned long long a, unsigned long long b) {
    unsigned long long r;
    asm("mul.rn.f32x2 %0, %1, %2;" : "=l"(r) : "l"(a), "l"(b));
    return r;
}
__device__ __forceinline__ unsigned long long fma2(unsigned long long a, unsigned long long b,
                                                   unsigned long long c) {
    unsigned long long r;
    asm("fma.rn.f32x2 %0, %1, %2, %3;" : "=l"(r) : "l"(a), "l"(b), "l"(c));
    return r;
}

__device__ __forceinline__ bool all_uniform() {
    const int4* p = (const int4*)g_uni;
    int u = 1;
#pragma unroll
    for (int i = 0; i < 16; ++i) {
        const int4 v = p[i];
        u &= v.x & v.y & v.z & v.w;
    }
    return u != 0;
}

// ================= setup: coefficients + uniformity + flag reset =========
// 64 blocks x 128 threads: 8 threads per d, 8 states per thread.
__global__ __launch_bounds__(128)
void ssm_setup_kernel(const float* __restrict__ log_A,
                      const float* __restrict__ Bp,
                      const float* __restrict__ Cp)
{
    __shared__ int s_uni;
    if (threadIdx.x == 0) s_uni = 1;
    __syncthreads();

    const int tid = threadIdx.x;
    if (blockIdx.x < 4) g_flag[blockIdx.x * 128 + tid] = 0;

    const int d    = blockIdx.x * 16 + (tid >> 3);
    const int n0   = (tid & 7) * 8;
    const int base = d * NSTATE + n0;

    const float4 la0 = *(const float4*)&log_A[base];
    const float4 la1 = *(const float4*)&log_A[base + 4];
    const float4 bp0 = *(const float4*)&Bp[base];
    const float4 bp1 = *(const float4*)&Bp[base + 4];
    const float4 cp0 = *(const float4*)&Cp[base];
    const float4 cp1 = *(const float4*)&Cp[base + 4];

    float la[8] = {la0.x, la0.y, la0.z, la0.w, la1.x, la1.y, la1.z, la1.w};
    float bp[8] = {bp0.x, bp0.y, bp0.z, bp0.w, bp1.x, bp1.y, bp1.z, bp1.w};
    float cp[8] = {cp0.x, cp0.y, cp0.z, cp0.w, cp1.x, cp1.y, cp1.z, cp1.w};

    float K = 0.0f, a[8];
    bool uni = true;
#pragma unroll
    for (int j = 0; j < 8; ++j) {
        const float A = -expf(la[j]);
        a[j] = expf(DT * A);
        K += (a[j] - 1.0f) / A * bp[j] * cp[j];
        uni = uni && (__float_as_int(a[j]) == __float_as_int(a[0]));
    }
    const float aref = __shfl_sync(0xFFFFFFFFu, a[0], (tid & 31) & ~7);
    uni = uni && (__float_as_int(a[0]) == __float_as_int(aref));

#pragma unroll
    for (int off = 1; off < 8; off <<= 1)
        K += __shfl_xor_sync(0xFFFFFFFFu, K, off);

    if ((tid & 7) == 0) { g_K[d] = K; g_a[d] = aref; }
    if (__ballot_sync(0xFFFFFFFFu, !uni) != 0) s_uni = 0;   // benign race
    __syncthreads();
    if (threadIdx.x == 0) g_uni[blockIdx.x] = s_uni;
}

// ================= fused scan: fast chunked path + general fallback ======
constexpr int T    = 32;
constexpr int NR   = L / T;
constexpr int XSTR = 40;

__global__ __launch_bounds__(256)
void ssm_fused_kernel(const float* __restrict__ x,
                      const float* __restrict__ log_A,
                      const float* __restrict__ Bp,
                      const float* __restrict__ Cp,
                      const float* __restrict__ Dp,
                      float* __restrict__ y)
{
    __shared__ float xs[8][2][4 * XSTR];    // general path only (10 KB)

    const int tid = threadIdx.x;
    const int bid = blockIdx.x;

    if (all_uniform()) {
        // ---------------- fast path: chunked scan with in-kernel carries --
        const int dg = bid & (DG - 1);
        const int c  = (bid >> 2) & (C - 1);
        const int b  = bid >> 6;
        const int d  = dg * DPG + tid;

        const float a  = g_a[d];
        const float K  = g_K[d];
        const float Dd = Dp[d];

        const float* xc = x + ((long)b * L + c * CH) * D_MODEL + d;
        float*       yc = y + ((long)b * L + c * CH) * D_MODEL + d;

        // pass 1: own chunk end-state (skipped for last chunk: never used)
        if (c < C - 1) {
            float u = 0.0f;
            float buf0[16], buf1[16];
#pragma unroll
            for (int j = 0; j < 16; ++j) buf0[j] = xc[j * D_MODEL];
#pragma unroll
            for (int bt = 0; bt < NB; ++bt) {
                float* cur = (bt & 1) ? buf1 : buf0;
                float* nxt = (bt & 1) ? buf0 : buf1;
                if (bt + 1 < NB) {
#pragma unroll
                    for (int j = 0; j < 16; ++j)
                        nxt[j] = xc[((bt + 1) * 16 + j) * D_MODEL];
                }
#pragma unroll
                for (int j = 0; j < 16; ++j)
                    u = fmaf(a, u, cur[j]);
            }
            g_S[(b * C + c) * D_MODEL + d] = u;
            __threadfence();
            __syncthreads();
            if (tid == 0)
                atomicExch(&g_flag[(b * C + c) * DG + dg], 1);
        }

        // a^CH via squarings (CH = 128 = 2^7)
        float ap = a;
#pragma unroll
        for (int k = 0; k < 7; ++k) ap *= ap;

        // wait for predecessors, then exact Horner seed
        float u = 0.0f;
        if (c > 0) {
            if (tid < c) {
                while (atomicAdd(&g_flag[(b * C + tid) * DG + dg], 0) == 0)
                    __nanosleep(128);
                __threadfence();
            }
            __syncthreads();
            for (int j = 0; j < c; ++j)
                u = fmaf(ap, u, g_S[(b * C + j) * D_MODEL + d]);
        }

        // pass 2: replay own chunk (L2-hot), write y
        {
            float buf0[16], buf1[16];
#pragma unroll
            for (int j = 0; j < 16; ++j) buf0[j] = xc[j * D_MODEL];
#pragma unroll
            for (int bt = 0; bt < NB; ++bt) {
                float* cur = (bt & 1) ? buf1 : buf0;
                float* nxt = (bt & 1) ? buf0 : buf1;
                if (bt + 1 < NB) {
#pragma unroll
                    for (int j = 0; j < 16; ++j)
                        nxt[j] = xc[((bt + 1) * 16 + j) * D_MODEL];
                }
#pragma unroll
                for (int j = 0; j < 16; ++j) {
                    const float xv = cur[j];
                    u = fmaf(a, u, xv);
                    yc[(bt * 16 + j) * D_MODEL] = fmaf(Dd, xv, K * u);
                }
            }
        }
        return;
    }

    // ---------------- general fallback (R5 logic, 8 warps / 32 d per blk) -
    if (bid >= 256) return;                 // fallback uses 256 blocks only
    const int b     = bid >> 5;
    const int d0blk = (bid & 31) * 32;
    const int w     = tid >> 5;
    const int lane  = tid & 31;
    const int g     = lane >> 3;
    const int gl    = lane & 7;
    const int d0w   = d0blk + w * 4;
    const int d     = d0w + g;

    unsigned long long a01[4], k01[4];
    {
        const int cb = d * NSTATE + gl * 4;
        const float4 laL = *(const float4*)&log_A[cb];
        const float4 laH = *(const float4*)&log_A[cb + 32];
        const float4 bL  = *(const float4*)&Bp[cb];
        const float4 bH  = *(const float4*)&Bp[cb + 32];
        const float4 cL  = *(const float4*)&Cp[cb];
        const float4 cH  = *(const float4*)&Cp[cb + 32];
        const float* laLp = &laL.x; const float* laHp = &laH.x;
        const float* bLp  = &bL.x;  const float* bHp  = &bH.x;
        const float* cLp  = &cL.x;  const float* cHp  = &cH.x;
#pragma unroll
        for (int j = 0; j < 4; ++j) {
            const float AL = -expf(laLp[j]);
            const float AH = -expf(laHp[j]);
            const float aL = expf(DT * AL);
            const float aH = expf(DT * AH);
            a01[j] = pack2(aL, aH);
            k01[j] = pack2((aL - 1.0f) / AL * bLp[j] * cLp[j],
                           (aH - 1.0f) / AH * bHp[j] * cHp[j]);
        }
    }

    const int si = lane >> 2;
    const int sj = lane & 3;
    const float Dd = Dp[d0w + sj];
    const float* xg = x + (long)b * L * D_MODEL + d0w + sj;
    float*       yg = y + (long)b * L * D_MODEL + d0w + sj;

    float xpre[4], xcur[4];
#pragma unroll
    for (int k = 0; k < 4; ++k)
        xpre[k] = xg[(si + 8 * k) * D_MODEL];

    unsigned long long u0 = 0ull, u1 = 0ull, u2 = 0ull, u3 = 0ull;

    for (int r = 0; r < NR; ++r) {
        const int l0 = r * T;
        float* xb = xs[w][r & 1];
#pragma unroll
        for (int k = 0; k < 4; ++k) {
            xcur[k] = xpre[k];
            xb[sj * XSTR + si + 8 * k] = xpre[k];
        }
        __syncwarp();
        if (r + 1 < NR) {
#pragma unroll
            for (int k = 0; k < 4; ++k)
                xpre[k] = xg[(l0 + T + si + 8 * k) * D_MODEL];
        }

        float y_out[4];
#pragma unroll
        for (int tb = 0; tb < T; tb += 16) {
            float v[16];
#pragma unroll
            for (int q = 0; q < 16; q += 4) {
                const float4 xq = *(const float4*)&xb[g * XSTR + tb + q];
                const float* xe = &xq.x;
#pragma unroll
                for (int i2 = 0; i2 < 4; ++i2) {
                    const unsigned long long xx = pack2(xe[i2], xe[i2]);
                    u0 = fma2(a01[0], u0, xx);
                    u1 = fma2(a01[1], u1, xx);
                    u2 = fma2(a01[2], u2, xx);
                    u3 = fma2(a01[3], u3, xx);
                    unsigned long long acc = mul2(k01[0], u0);
                    acc = fma2(k01[1], u1, acc);
                    acc = fma2(k01[2], u2, acc);
                    float lo, hi;
                    unpack2(fma2(k01[3], u3, acc), lo, hi);
                    v[q + i2] = lo + hi;
                }
            }
            {
                const bool h4 = (gl & 4) != 0;
#pragma unroll
                for (int ii = 0; ii < 8; ++ii) {
                    const int i = (ii < 4) ? ii : ii + 4;
                    const float send = h4 ? v[i] : v[i + 4];
                    const float keep = h4 ? v[i + 4] : v[i];
                    v[i] = keep + __shfl_xor_sync(0xFFFFFFFFu, send, 4);
                }
                const bool h2 = (gl & 2) != 0;
#pragma unroll
                for (int ii = 0; ii < 4; ++ii) {
                    const int i = (ii < 2) ? ii : ii + 6;
                    const float send = h2 ? v[i] : v[i + 2];
                    const float keep = h2 ? v[i + 2] : v[i];
                    v[i] = keep + __shfl_xor_sync(0xFFFFFFFFu, send, 2);
                }
                const bool h1 = (gl & 1) != 0;
#pragma unroll
                for (int ii = 0; ii < 2; ++ii) {
                    const int i = ii * 8;
                    const float send = h1 ? v[i] : v[i + 1];
                    const float keep = h1 ? v[i + 1] : v[i];
                    v[i] = keep + __shfl_xor_sync(0xFFFFFFFFu, send, 1);
                }
            }
            const int srcLane = sj * 8 + si;
            y_out[tb / 8]     = __shfl_sync(0xFFFFFFFFu, v[0], srcLane);
            y_out[tb / 8 + 1] = __shfl_sync(0xFFFFFFFFu, v[8], srcLane);
        }
#pragma unroll
        for (int k = 0; k < 4; ++k)
            yg[(l0 + si + 8 * k) * D_MODEL] = fmaf(Dd, xcur[k], y_out[k]);
    }
}

} // namespace

extern "C" void kernel_launch(void* const* d_in, const int* in_sizes, int n_in,
                              void* d_out, int out_size)
{
    const float* x     = (const float*)d_in[0];
    const float* log_A = (const float*)d_in[1];
    const float* Bp    = (const float*)d_in[2];
    const float* Cp    = (const float*)d_in[3];
    const float* Dp    = (const float*)d_in[4];
    float* y           = (float*)d_out;

    ssm_setup_kernel<<<64, 128>>>(log_A, Bp, Cp);
    ssm_fused_kernel<<<DG * C * BATCH, 256>>>(x, log_A, Bp, Cp, Dp, y);
}